// round 13
// baseline (speedup 1.0000x reference)
#include <cuda_runtime.h>

#define B 32
#define S 4096
#define DIN 1024
#define DOUT 256
#define NSEG 64
#define TILE_S 128
#define TILE_M 16

// scratch (static; zero-init at load; gemm re-zeroes g_segsum every call)
__device__ float g_segsum[(size_t)B * NSEG * DIN];                 // 8 MB
__device__ float g_zp[2][(size_t)B * NSEG * DOUT];                 // 2 x 2 MB

// ---------------------------------------------------------------------------
// Kernel 1: segment-reduce, HALF the batches per launch (b0 = 0 or 16).
// Same proven body as R9 (at HBM wall).
// ---------------------------------------------------------------------------
__global__ void __launch_bounds__(256, 7) seg_tile_kernel(
    const float* __restrict__ enc,
    const int*   __restrict__ cls_pos,
    const int*   __restrict__ last_sep,
    int b0)
{
    const int b    = b0 + blockIdx.y;
    const int tile = blockIdx.x;
    const int tid  = threadIdx.x;

    __shared__ int sstart[NSEG];
    if (tid < NSEG) sstart[tid] = cls_pos[b * NSEG + tid];
    __syncthreads();

    const int e_sep    = last_sep[b] + 1;
    const int end_last = (e_sep > sstart[NSEG - 1]) ? e_sep : S;

    const int s0 = tile * TILE_S;
    const int s1 = s0 + TILE_S;

    int seg = -1;
    while (seg < NSEG - 1 && sstart[seg + 1] <= s0) seg++;
    int nxt = (seg < NSEG - 1) ? sstart[seg + 1] : 0x7fffffff;

    const float4* __restrict__ p = reinterpret_cast<const float4*>(enc)
                                 + (size_t)b * S * (DIN / 4) + tid;

    float4 acc = make_float4(0.f, 0.f, 0.f, 0.f);
    int acc_seg = seg;

#define FLUSH_ACC()                                                           \
    do { if (acc_seg >= 0) {                                                  \
        float* d_ = g_segsum + (size_t)(b * NSEG + acc_seg) * DIN + tid * 4;  \
        atomicAdd(d_ + 0, acc.x); atomicAdd(d_ + 1, acc.y);                   \
        atomicAdd(d_ + 2, acc.z); atomicAdd(d_ + 3, acc.w);                   \
    } } while (0)

    for (int base = s0; base < s1; base += 4) {
        float4 v0 = __ldcs(&p[(size_t)(base + 0) * (DIN / 4)]);
        float4 v1 = __ldcs(&p[(size_t)(base + 1) * (DIN / 4)]);
        float4 v2 = __ldcs(&p[(size_t)(base + 2) * (DIN / 4)]);
        float4 v3 = __ldcs(&p[(size_t)(base + 3) * (DIN / 4)]);

        if (seg >= 0 && base + 3 < nxt &&
            (seg < NSEG - 1 || base + 3 < end_last)) {
            acc.x += (v0.x + v1.x) + (v2.x + v3.x);
            acc.y += (v0.y + v1.y) + (v2.y + v3.y);
            acc.z += (v0.z + v1.z) + (v2.z + v3.z);
            acc.w += (v0.w + v1.w) + (v2.w + v3.w);
        } else {
            float4 v[4] = {v0, v1, v2, v3};
#pragma unroll
            for (int j = 0; j < 4; ++j) {
                const int r = base + j;
                if (r >= nxt) {
                    while (seg < NSEG - 1 && r >= sstart[seg + 1]) seg++;
                    nxt = (seg < NSEG - 1) ? sstart[seg + 1] : 0x7fffffff;
                    FLUSH_ACC();
                    acc = make_float4(0.f, 0.f, 0.f, 0.f);
                    acc_seg = seg;
                }
                const bool ok = (seg >= 0) && (seg < NSEG - 1 || r < end_last);
                if (ok) {
                    acc.x += v[j].x; acc.y += v[j].y;
                    acc.z += v[j].z; acc.w += v[j].w;
                }
            }
        }
    }
    FLUSH_ACC();
#undef FLUSH_ACC
}

// ---------------------------------------------------------------------------
// Kernel 2: partial GEMM. Block = (m-tile, k-half): 16 rows x 256 cols over
// K=512. Internals = R9 (proven): 512 thr = (k-128th q, row-half rh, col-quad
// cq), packed fma.rn.f32x2, one-shot A stage, 2-sync 4-buffer combine.
// Writes 16x256 partial z to g_zp[kh]; re-zeroes its own (rows x k-half)
// slice of g_segsum.
// ---------------------------------------------------------------------------
__global__ void __launch_bounds__(512, 1) gemm_part_kernel(
    const float* __restrict__ Wm, int moff)
{
    extern __shared__ float sm[];              // 16384 floats = 64KB

    const int tid = threadIdx.x;
    const int mt  = moff + (blockIdx.x >> 1);
    const int kh  = blockIdx.x & 1;
    const int m0  = mt * TILE_M;
    const int kb  = kh * 512;

    const int q   = tid >> 7;                  // k-128th 0..3 within the half
    const int rh  = (tid >> 6) & 1;
    const int cq  = tid & 63;

    // ---- stage A transposed: sm[k*20 + i], k in [0,512) local
    {
        const int i  = tid >> 5;               // row 0..15
        const int kl = tid & 31;
        const float* src = g_segsum + (size_t)(m0 + i) * DIN + kb + kl;
#pragma unroll
        for (int j = 0; j < 16; ++j)
            sm[(kl + 32 * j) * 20 + i] = src[32 * j];
    }
    __syncthreads();

    // ---- re-zero this block's (16 rows x 512 k) slice of g_segsum
#pragma unroll
    for (int r = 0; r < 4; ++r) {
        const int flat = r * 512 + tid;        // 0..2047
        const int row  = flat >> 7;
        const int c4   = flat & 127;
        *reinterpret_cast<float4*>(g_segsum + (size_t)(m0 + row) * DIN + kb + c4 * 4)
            = make_float4(0.f, 0.f, 0.f, 0.f);
    }

    // ---- mainloop (R9 body, 128 k per q)
    unsigned long long acc2[16];
#pragma unroll
    for (int x = 0; x < 16; ++x) acc2[x] = 0ull;

    const float4* Wp = reinterpret_cast<const float4*>(Wm)
                     + (size_t)(kb + q * 128) * (DOUT / 4) + cq;
    const float* aBase = sm + (size_t)(q * 128) * 20 + rh * 8;

    for (int kk = 0; kk < 128; kk += 4) {
        float4 w[4];
#pragma unroll
        for (int j = 0; j < 4; ++j) w[j] = Wp[(size_t)(kk + j) * (DOUT / 4)];
#pragma unroll
        for (int j = 0; j < 4; ++j) {
            const ulonglong2* ap =
                reinterpret_cast<const ulonglong2*>(aBase + (kk + j) * 20);
            ulonglong2 a01 = ap[0];
            ulonglong2 a23 = ap[1];
            unsigned long long wp0, wp1, wp2, wp3;
            asm("mov.b64 %0, {%1,%1};" : "=l"(wp0) : "f"(w[j].x));
            asm("mov.b64 %0, {%1,%1};" : "=l"(wp1) : "f"(w[j].y));
            asm("mov.b64 %0, {%1,%1};" : "=l"(wp2) : "f"(w[j].z));
            asm("mov.b64 %0, {%1,%1};" : "=l"(wp3) : "f"(w[j].w));
#define FMA2(idx, apair, wpair) \
            asm("fma.rn.f32x2 %0, %1, %2, %3;" : "=l"(acc2[idx]) : "l"(apair), "l"(wpair), "l"(acc2[idx]))
            FMA2(0,  a01.x, wp0); FMA2(1,  a01.x, wp1); FMA2(2,  a01.x, wp2); FMA2(3,  a01.x, wp3);
            FMA2(4,  a01.y, wp0); FMA2(5,  a01.y, wp1); FMA2(6,  a01.y, wp2); FMA2(7,  a01.y, wp3);
            FMA2(8,  a23.x, wp0); FMA2(9,  a23.x, wp1); FMA2(10, a23.x, wp2); FMA2(11, a23.x, wp3);
            FMA2(12, a23.y, wp0); FMA2(13, a23.y, wp1); FMA2(14, a23.y, wp2); FMA2(15, a23.y, wp3);
#undef FMA2
        }
    }

    float accf[8][4];
#pragma unroll
    for (int rp = 0; rp < 4; ++rp)
#pragma unroll
        for (int c = 0; c < 4; ++c) {
            float lo, hi;
            asm("mov.b64 {%0,%1}, %2;" : "=f"(lo), "=f"(hi) : "l"(acc2[rp * 4 + c]));
            accf[2 * rp][c]     = lo;
            accf[2 * rp + 1][c] = hi;
        }

    // ---- combine: barrier, each q writes its buffer, barrier
    __syncthreads();
    {
        const int rbase = rh * 8;
        float4* d_ = reinterpret_cast<float4*>(sm + q * 4096 + cq * 4);
#pragma unroll
        for (int r = 0; r < 8; ++r)
            d_[(rbase + r) * (DOUT / 4)] =
                make_float4(accf[r][0], accf[r][1], accf[r][2], accf[r][3]);
    }
    __syncthreads();

    // ---- warp w (0..15) sums the 4 buffers for row w -> g_zp[kh]
    const int wid  = tid >> 5;
    const int lane = tid & 31;
    {
        const float* z0 = sm + 0 * 4096 + wid * DOUT;
        const float* z1 = sm + 1 * 4096 + wid * DOUT;
        const float* z2 = sm + 2 * 4096 + wid * DOUT;
        const float* z3 = sm + 3 * 4096 + wid * DOUT;
        float* dst = g_zp[kh] + (size_t)(m0 + wid) * DOUT;
#pragma unroll
        for (int j = 0; j < 8; ++j) {
            const int cc = lane + 32 * j;
            dst[cc] = (z0[cc] + z1[cc]) + (z2[cc] + z3[cc]);
        }
    }
}

// ---------------------------------------------------------------------------
// Kernel 3: z = zp0 + zp1 + cnt*bias; log_softmax; write out. Warp per row.
// ---------------------------------------------------------------------------
__global__ void __launch_bounds__(256) lsm_kernel(
    const float* __restrict__ bias,
    const int*   __restrict__ cls_pos,
    const int*   __restrict__ last_sep,
    float*       __restrict__ out)
{
    const int wid  = threadIdx.x >> 5;
    const int lane = threadIdx.x & 31;
    const int g    = blockIdx.x * 8 + wid;
    const int bb   = g >> 6;
    const int nn   = g & (NSEG - 1);

    const int start = cls_pos[bb * NSEG + nn];
    int end;
    if (nn < NSEG - 1) end = cls_pos[bb * NSEG + nn + 1];
    else { int e2 = last_sep[bb] + 1; end = (e2 > start) ? e2 : S; }
    const float cnt = (float)(end - start);

    const float* zr0 = g_zp[0] + (size_t)g * DOUT;
    const float* zr1 = g_zp[1] + (size_t)g * DOUT;

    float z[8];
    float m = __int_as_float(0xff800000);
#pragma unroll
    for (int j = 0; j < 8; ++j) {
        const int cc = lane + 32 * j;
        z[j] = fmaf(cnt, bias[cc], zr0[cc] + zr1[cc]);
        m = fmaxf(m, z[j]);
    }
#pragma unroll
    for (int off = 16; off > 0; off >>= 1)
        m = fmaxf(m, __shfl_xor_sync(0xffffffffu, m, off));
    float ss = 0.f;
#pragma unroll
    for (int j = 0; j < 8; ++j) ss += expf(z[j] - m);
#pragma unroll
    for (int off = 16; off > 0; off >>= 1)
        ss += __shfl_xor_sync(0xffffffffu, ss, off);
    const float lse = m + logf(ss);
    float* op = out + (size_t)g * DOUT;
#pragma unroll
    for (int j = 0; j < 8; ++j)
        op[lane + 32 * j] = z[j] - lse;
}

// ---------------------------------------------------------------------------
extern "C" void kernel_launch(void* const* d_in, const int* in_sizes, int n_in,
                              void* d_out, int out_size)
{
    const float* enc  = nullptr;
    const float* Wm   = nullptr;
    const float* bias = nullptr;
    const int*   cls  = nullptr;
    const int*   ls   = nullptr;
    for (int i = 0; i < n_in; ++i) {
        switch (in_sizes[i]) {
            case 134217728: enc  = (const float*)d_in[i]; break;
            case 262144:    Wm   = (const float*)d_in[i]; break;
            case 256:       bias = (const float*)d_in[i]; break;
            case 2048:      cls  = (const int*)d_in[i];   break;
            case 32:        ls   = (const int*)d_in[i];   break;
            default: break;
        }
    }

    // one-time handles (created on the uncaptured correctness call; every
    // call afterwards issues the identical launch/event sequence)
    static cudaStream_t s1 = nullptr;
    static cudaEvent_t  e1 = nullptr, e2 = nullptr, e3 = nullptr;
    if (!s1) {
        cudaStreamCreateWithFlags(&s1, cudaStreamNonBlocking);
        cudaEventCreateWithFlags(&e1, cudaEventDisableTiming);
        cudaEventCreateWithFlags(&e2, cudaEventDisableTiming);
        cudaEventCreateWithFlags(&e3, cudaEventDisableTiming);
    }

    const int smem_bytes = 16384 * (int)sizeof(float);   // 64 KB
    cudaFuncSetAttribute(gemm_part_kernel,
                         cudaFuncAttributeMaxDynamicSharedMemorySize, smem_bytes);

    // s0 (launch/capture stream): two seg halves
    dim3 gs(S / TILE_S, B / 2);
    seg_tile_kernel<<<gs, 256>>>(enc, cls, ls, 0);
    cudaEventRecord(e1, 0);
    seg_tile_kernel<<<gs, 256>>>(enc, cls, ls, 16);
    cudaEventRecord(e2, 0);

    // s1: gemm halves chase the seg halves; lsm finishes
    cudaStreamWaitEvent(s1, e1, 0);
    gemm_part_kernel<<<128, 512, smem_bytes, s1>>>(Wm, 0);    // rows 0..1023
    cudaStreamWaitEvent(s1, e2, 0);
    gemm_part_kernel<<<128, 512, smem_bytes, s1>>>(Wm, 64);   // rows 1024..2047
    lsm_kernel<<<(B * NSEG) / 8, 256, 0, s1>>>(bias, cls, ls, (float*)d_out);
    cudaEventRecord(e3, s1);

    // rejoin the fork before returning
    cudaStreamWaitEvent(0, e3, 0);
}

// round 14
// speedup vs baseline: 1.2373x; 1.2373x over previous
#include <cuda_runtime.h>

#define B 32
#define S 4096
#define DIN 1024
#define DOUT 256
#define NSEG 64
#define TILE_S 128    // rows of S per block in the segment-reduce kernel
#define TILE_M 16     // segment rows per block in the GEMM kernel

// 8 MB scratch: per-(batch,segment) sums over D_IN.
// Zero-initialized at module load; gemm_lsm_kernel re-zeroes it every call.
__device__ float g_segsum[(size_t)B * NSEG * DIN];

// ---------------------------------------------------------------------------
// Kernel 1: segment-reduce enc_output over S — balanced uniform tiles.
// (R9 body, unchanged: measured ~7 TB/s, at the HBM wall)
// ---------------------------------------------------------------------------
__global__ void __launch_bounds__(256, 7) seg_tile_kernel(
    const float* __restrict__ enc,
    const int*   __restrict__ cls_pos,
    const int*   __restrict__ last_sep)
{
    const int b    = blockIdx.y;
    const int tile = blockIdx.x;
    const int tid  = threadIdx.x;

    __shared__ int sstart[NSEG];
    if (tid < NSEG) sstart[tid] = cls_pos[b * NSEG + tid];
    __syncthreads();

    const int e_sep    = last_sep[b] + 1;
    const int end_last = (e_sep > sstart[NSEG - 1]) ? e_sep : S;  // torch rule

    const int s0 = tile * TILE_S;
    const int s1 = s0 + TILE_S;

    int seg = -1;
    while (seg < NSEG - 1 && sstart[seg + 1] <= s0) seg++;
    int nxt = (seg < NSEG - 1) ? sstart[seg + 1] : 0x7fffffff;

    const float4* __restrict__ p = reinterpret_cast<const float4*>(enc)
                                 + (size_t)b * S * (DIN / 4) + tid;

    float4 acc = make_float4(0.f, 0.f, 0.f, 0.f);
    int acc_seg = seg;

#define FLUSH_ACC()                                                           \
    do { if (acc_seg >= 0) {                                                  \
        float* d_ = g_segsum + (size_t)(b * NSEG + acc_seg) * DIN + tid * 4;  \
        atomicAdd(d_ + 0, acc.x); atomicAdd(d_ + 1, acc.y);                   \
        atomicAdd(d_ + 2, acc.z); atomicAdd(d_ + 3, acc.w);                   \
    } } while (0)

    for (int base = s0; base < s1; base += 4) {
        float4 v0 = __ldcs(&p[(size_t)(base + 0) * (DIN / 4)]);
        float4 v1 = __ldcs(&p[(size_t)(base + 1) * (DIN / 4)]);
        float4 v2 = __ldcs(&p[(size_t)(base + 2) * (DIN / 4)]);
        float4 v3 = __ldcs(&p[(size_t)(base + 3) * (DIN / 4)]);

        if (seg >= 0 && base + 3 < nxt &&
            (seg < NSEG - 1 || base + 3 < end_last)) {
            acc.x += (v0.x + v1.x) + (v2.x + v3.x);
            acc.y += (v0.y + v1.y) + (v2.y + v3.y);
            acc.z += (v0.z + v1.z) + (v2.z + v3.z);
            acc.w += (v0.w + v1.w) + (v2.w + v3.w);
        } else {
            float4 v[4] = {v0, v1, v2, v3};
#pragma unroll
            for (int j = 0; j < 4; ++j) {
                const int r = base + j;
                if (r >= nxt) {
                    while (seg < NSEG - 1 && r >= sstart[seg + 1]) seg++;
                    nxt = (seg < NSEG - 1) ? sstart[seg + 1] : 0x7fffffff;
                    FLUSH_ACC();
                    acc = make_float4(0.f, 0.f, 0.f, 0.f);
                    acc_seg = seg;
                }
                const bool ok = (seg >= 0) && (seg < NSEG - 1 || r < end_last);
                if (ok) {
                    acc.x += v[j].x; acc.y += v[j].y;
                    acc.z += v[j].z; acc.w += v[j].w;
                }
            }
        }
    }
    FLUSH_ACC();
#undef FLUSH_ACC
}

// ---------------------------------------------------------------------------
// Kernel 2: R9 gemm+lsm body, with a PDL prologue: prefetch this block's 8KB
// slice of W into L2 (independent of seg output), THEN grid-dependency-sync,
// then proceed exactly as the measured-best R9 kernel.
// ---------------------------------------------------------------------------
__global__ void __launch_bounds__(512, 1) gemm_lsm_kernel(
    const float* __restrict__ Wm,
    const float* __restrict__ bias,
    const int*   __restrict__ cls_pos,
    const int*   __restrict__ last_sep,
    float*       __restrict__ out)
{
    extern __shared__ float sm[];              // 1024*20 floats = 80KB
    __shared__ float sBias[DOUT];

    const int tid = threadIdx.x;
    const int q   = tid >> 7;                  // k-quarter 0..3 (256 k each)
    const int rh  = (tid >> 6) & 1;            // row half 0..1  (8 rows each)
    const int cq  = tid & 63;                  // col quad 0..63 (4 cols each)
    const int m0  = blockIdx.x * TILE_M;

    // ---- PDL prologue: warm L2 with this block's W slice (8 rows x 256 cols
    // = 8KB; 128 blocks cover all of W). Does NOT read seg output.
    if (tid < 64) {
        const char* wp = reinterpret_cast<const char*>(
            Wm + (size_t)blockIdx.x * 8 * DOUT) + tid * 128;
        asm volatile("prefetch.global.L2 [%0];" :: "l"(wp));
    }

#if defined(__CUDA_ARCH__) && (__CUDA_ARCH__ >= 900)
    cudaGridDependencySynchronize();           // wait for seg_tile_kernel
#endif

    if (tid < DOUT) sBias[tid] = bias[tid];

    // ---- stage A transposed: sm[k*20 + i] (one shot, one sync)
    {
        const int i  = tid >> 5;               // row 0..15
        const int kl = tid & 31;               // k lane
        const float* src = g_segsum + (size_t)(m0 + i) * DIN + kl;
#pragma unroll
        for (int j = 0; j < 32; ++j)
            sm[(kl + 32 * j) * 20 + i] = src[32 * j];
    }
    __syncthreads();

    // ---- restore g_segsum rows to zero for the next call (fire-and-forget)
    {
        float4* z = reinterpret_cast<float4*>(g_segsum + (size_t)m0 * DIN);
        const float4 z4 = make_float4(0.f, 0.f, 0.f, 0.f);
#pragma unroll
        for (int r = 0; r < 8; ++r) z[r * 512 + tid] = z4;
    }

    // ---- mainloop: acc2[rp*4+c] = packed rows {2rp, 2rp+1} of column 4cq+c
    unsigned long long acc2[16];
#pragma unroll
    for (int x = 0; x < 16; ++x) acc2[x] = 0ull;

    const float4* Wp = reinterpret_cast<const float4*>(Wm)
                     + (size_t)(q * 256) * (DOUT / 4) + cq;
    const float* aBase = sm + (size_t)(q * 256) * 20 + rh * 8;

    for (int kk = 0; kk < 256; kk += 4) {
        float4 w[4];
#pragma unroll
        for (int j = 0; j < 4; ++j) w[j] = Wp[(size_t)(kk + j) * (DOUT / 4)];
#pragma unroll
        for (int j = 0; j < 4; ++j) {
            const ulonglong2* ap =
                reinterpret_cast<const ulonglong2*>(aBase + (kk + j) * 20);
            ulonglong2 a01 = ap[0];   // row-pairs 0,1 (rows rbase+0..3)
            ulonglong2 a23 = ap[1];   // row-pairs 2,3 (rows rbase+4..7)
            unsigned long long wp0, wp1, wp2, wp3;
            asm("mov.b64 %0, {%1,%1};" : "=l"(wp0) : "f"(w[j].x));
            asm("mov.b64 %0, {%1,%1};" : "=l"(wp1) : "f"(w[j].y));
            asm("mov.b64 %0, {%1,%1};" : "=l"(wp2) : "f"(w[j].z));
            asm("mov.b64 %0, {%1,%1};" : "=l"(wp3) : "f"(w[j].w));
#define FMA2(idx, apair, wpair) \
            asm("fma.rn.f32x2 %0, %1, %2, %3;" : "=l"(acc2[idx]) : "l"(apair), "l"(wpair), "l"(acc2[idx]))
            FMA2(0,  a01.x, wp0); FMA2(1,  a01.x, wp1); FMA2(2,  a01.x, wp2); FMA2(3,  a01.x, wp3);
            FMA2(4,  a01.y, wp0); FMA2(5,  a01.y, wp1); FMA2(6,  a01.y, wp2); FMA2(7,  a01.y, wp3);
            FMA2(8,  a23.x, wp0); FMA2(9,  a23.x, wp1); FMA2(10, a23.x, wp2); FMA2(11, a23.x, wp3);
            FMA2(12, a23.y, wp0); FMA2(13, a23.y, wp1); FMA2(14, a23.y, wp2); FMA2(15, a23.y, wp3);
#undef FMA2
        }
    }

    // unpack: accf[r][c], r = row within half (0..7), c = col within quad
    float accf[8][4];
#pragma unroll
    for (int rp = 0; rp < 4; ++rp)
#pragma unroll
        for (int c = 0; c < 4; ++c) {
            float lo, hi;
            asm("mov.b64 {%0,%1}, %2;" : "=f"(lo), "=f"(hi) : "l"(acc2[rp * 4 + c]));
            accf[2 * rp][c]     = lo;
            accf[2 * rp + 1][c] = hi;
        }

    // ---- combine: barrier FIRST (A tile must be dead in ALL warps before
    // any buffer write), quarter q writes buf q, barrier, epilogue sums 4.
    __syncthreads();
    {
        const int rbase = rh * 8;
        float4* d_ = reinterpret_cast<float4*>(sm + q * 4096 + cq * 4);
#pragma unroll
        for (int r = 0; r < 8; ++r)
            d_[(rbase + r) * (DOUT / 4)] =
                make_float4(accf[r][0], accf[r][1], accf[r][2], accf[r][3]);
    }
    __syncthreads();

    // ---- barrier-free epilogue: warp w (0..15) owns row w; sums 4 buffers
    const int wid  = tid >> 5;
    const int lane = tid & 31;
    {
        const int g  = m0 + wid;
        const int bb = g >> 6;
        const int nn = g & (NSEG - 1);
        const int start = cls_pos[bb * NSEG + nn];
        int end;
        if (nn < NSEG - 1) end = cls_pos[bb * NSEG + nn + 1];
        else { int e2 = last_sep[bb] + 1; end = (e2 > start) ? e2 : S; }
        const float cnt = (float)(end - start);

        const float* z0 = sm + 0 * 4096 + wid * DOUT;
        const float* z1 = sm + 1 * 4096 + wid * DOUT;
        const float* z2 = sm + 2 * 4096 + wid * DOUT;
        const float* z3 = sm + 3 * 4096 + wid * DOUT;

        float z[8];
        float m = __int_as_float(0xff800000);  // -inf
#pragma unroll
        for (int j = 0; j < 8; ++j) {
            const int cc = lane + 32 * j;
            const float s01 = z0[cc] + z1[cc];
            const float s23 = z2[cc] + z3[cc];
            z[j] = fmaf(cnt, sBias[cc], s01 + s23);
            m = fmaxf(m, z[j]);
        }
#pragma unroll
        for (int off = 16; off > 0; off >>= 1)
            m = fmaxf(m, __shfl_xor_sync(0xffffffffu, m, off));

        float ssum = 0.f;
#pragma unroll
        for (int j = 0; j < 8; ++j) ssum += expf(z[j] - m);
#pragma unroll
        for (int off = 16; off > 0; off >>= 1)
            ssum += __shfl_xor_sync(0xffffffffu, ssum, off);

        const float lse = m + logf(ssum);
        float* op = out + (size_t)g * DOUT;
#pragma unroll
        for (int j = 0; j < 8; ++j)
            op[lane + 32 * j] = z[j] - lse;
    }
}

// ---------------------------------------------------------------------------
extern "C" void kernel_launch(void* const* d_in, const int* in_sizes, int n_in,
                              void* d_out, int out_size)
{
    const float* enc  = nullptr;
    const float* Wm   = nullptr;
    const float* bias = nullptr;
    const int*   cls  = nullptr;
    const int*   ls   = nullptr;
    for (int i = 0; i < n_in; ++i) {
        switch (in_sizes[i]) {
            case 134217728: enc  = (const float*)d_in[i]; break;
            case 262144:    Wm   = (const float*)d_in[i]; break;
            case 256:       bias = (const float*)d_in[i]; break;
            case 2048:      cls  = (const int*)d_in[i];   break;
            case 32:        ls   = (const int*)d_in[i];   break;
            default: break;
        }
    }

    // 1) balanced segment reduce into (pre-zeroed) g_segsum: single wave
    dim3 g1(S / TILE_S, B);
    seg_tile_kernel<<<g1, 256>>>(enc, cls, ls);

    // 2) GEMM + bias*count + log_softmax with PDL: blocks may be placed while
    //    seg drains; they prefetch W to L2, then grid-dependency-sync.
    const int smem_bytes = 1024 * 20 * (int)sizeof(float);   // 81920
    cudaFuncSetAttribute(gemm_lsm_kernel,
                         cudaFuncAttributeMaxDynamicSharedMemorySize, smem_bytes);

    cudaLaunchConfig_t cfg = {};
    cfg.gridDim          = dim3((B * NSEG) / TILE_M, 1, 1);
    cfg.blockDim         = dim3(512, 1, 1);
    cfg.dynamicSmemBytes = smem_bytes;
    cfg.stream           = 0;
    cudaLaunchAttribute attrs[1];
    attrs[0].id = cudaLaunchAttributeProgrammaticStreamSerialization;
    attrs[0].val.programmaticStreamSerializationAllowed = 1;
    cfg.attrs    = attrs;
    cfg.numAttrs = 1;

    cudaError_t err = cudaLaunchKernelEx(&cfg, gemm_lsm_kernel,
                                         Wm, bias, cls, ls, (float*)d_out);
    if (err != cudaSuccess) {
        // PDL unavailable in this context: fall back to a plain launch
        // (cudaGridDependencySynchronize is a no-op once the prior kernel
        // has completed on the same stream).
        gemm_lsm_kernel<<<(B * NSEG) / TILE_M, 512, smem_bytes>>>(
            Wm, bias, cls, ls, (float*)d_out);
    }
}